// round 11
// baseline (speedup 1.0000x reference)
#include <cuda_runtime.h>
#include <cuda_bf16.h>
#include <cstdint>

// CausalAttention via mma.sync bf16 hi/lo-split (3-MMA emulated fp32).
// R11: 256x128 CTA tile (64x64 warp tile) for 1.5x better ldmatrix:HMMA issue
// density and half the sync/load-issue overhead per MAC vs the 128x128 tile.

typedef unsigned int u32;
typedef unsigned long long u64;

#define TPB 256
#define BK 64                    // K-chunk in bf16 elems
#define LDSS 72                  // padded smem row (144B) - conflict-free ldmatrix
#define TILE_A (256 * LDSS * 2)  // 36864 B : 256x64 bf16 tile
#define TILE_BT (128 * LDSS * 2) // 18432 B : 128x64 bf16 tile
#define OFF_AH 0
#define OFF_AL TILE_A
#define OFF_BH (2 * TILE_A)
#define OFF_BL (2 * TILE_A + TILE_BT)
#define BUF_B (2 * TILE_A + 2 * TILE_BT)  // 110592
#define GEMM_SMEM (2 * BUF_B)             // 221184

// ---------------- scratch (no allocation anywhere) ----------------
__device__ __nv_bfloat16 g_xh[8192 * 1024];
__device__ __nv_bfloat16 g_xl[8192 * 1024];
__device__ __nv_bfloat16 g_WTh[3 * 1024 * 1024];
__device__ __nv_bfloat16 g_WTl[3 * 1024 * 1024];
__device__ __nv_bfloat16 g_Qh[4 * 2048 * 1024];
__device__ __nv_bfloat16 g_Ql[4 * 2048 * 1024];
__device__ __nv_bfloat16 g_Kh[4 * 2048 * 1024];
__device__ __nv_bfloat16 g_Kl[4 * 2048 * 1024];
__device__ float         g_V[4 * 2048 * 1024];
__device__ __nv_bfloat16 g_VTh[(size_t)4 * 1024 * 2048];
__device__ __nv_bfloat16 g_VTl[(size_t)4 * 1024 * 2048];
__device__ float         g_S[(size_t)4 * 2048 * 2048];
__device__ __nv_bfloat16 g_Ph[(size_t)4 * 2048 * 2048];
__device__ __nv_bfloat16 g_Pl[(size_t)4 * 2048 * 2048];

// ---------------- helpers ----------------
__device__ __forceinline__ u32 smem_u32(const void* p) {
    u32 a;
    asm("{ .reg .u64 t; cvta.to.shared.u64 t, %1; cvt.u32.u64 %0, t; }"
        : "=r"(a) : "l"(p));
    return a;
}

__device__ __forceinline__ void cp_async16(u32 dst, const void* src) {
    asm volatile("cp.async.cg.shared.global [%0], [%1], 16;"
                 :: "r"(dst), "l"(src) : "memory");
}
#define CP_COMMIT() asm volatile("cp.async.commit_group;" ::: "memory")
#define CP_WAIT(N)  asm volatile("cp.async.wait_group %0;" :: "n"(N) : "memory")

__device__ __forceinline__ void ldmx4(u32 a, u32& r0, u32& r1, u32& r2, u32& r3) {
    asm volatile("ldmatrix.sync.aligned.m8n8.x4.shared.b16 {%0,%1,%2,%3}, [%4];"
                 : "=r"(r0), "=r"(r1), "=r"(r2), "=r"(r3) : "r"(a));
}

__device__ __forceinline__ void mma16816(float c[4], const u32 a[4], const u32 b[2]) {
    asm volatile(
        "mma.sync.aligned.m16n8k16.row.col.f32.bf16.bf16.f32 "
        "{%0,%1,%2,%3}, {%4,%5,%6,%7}, {%8,%9}, {%0,%1,%2,%3};"
        : "+f"(c[0]), "+f"(c[1]), "+f"(c[2]), "+f"(c[3])
        : "r"(a[0]), "r"(a[1]), "r"(a[2]), "r"(a[3]), "r"(b[0]), "r"(b[1]));
}

__device__ __forceinline__ void split2(float v, __nv_bfloat16& h, __nv_bfloat16& l) {
    h = __float2bfloat16_rn(v);
    l = __float2bfloat16_rn(v - __bfloat162float(h));
}

// ---------------- GEMM core ----------------
// C[256x128 tile at (m0,n0)] = sum_k A[m,k]*B[n,k], A/B hi+lo bf16, K-major.
// MODE 0: fp32 out (Cf) * scale.   MODE 1: split bf16 out (Ch, Cl).
template <int MODE>
__device__ __forceinline__ void gemm_core(
    const __nv_bfloat16* __restrict__ Ah, const __nv_bfloat16* __restrict__ Al, int lda,
    const __nv_bfloat16* __restrict__ Bh, const __nv_bfloat16* __restrict__ Bl, int ldb,
    int m0, int n0, int Klen, float scale,
    float* __restrict__ Cf, __nv_bfloat16* __restrict__ Ch, __nv_bfloat16* __restrict__ Cl,
    int ldc)
{
    extern __shared__ char smem[];
    const u32 sbase = smem_u32(smem);
    const int tid = threadIdx.x;
    const int wid = tid >> 5;
    const int lane = tid & 31;
    const int warp_m = (wid & 3) * 64;   // 4 warps over M(256)
    const int warp_n = (wid >> 2) * 64;  // 2 warps over N(128)

    // cp.async mapping: 32 rows x 8 segs(16B) per pass; A: 8 passes, B: 4.
    const int lrow = tid >> 3;            // 0..31
    const int lseg = (tid & 7) * 8;       // elem col 0..56
    const u32 dst_off = (u32)(lrow * LDSS + lseg) * 2;
    const __nv_bfloat16* pAh = Ah + (size_t)(m0 + lrow) * lda + lseg;
    const __nv_bfloat16* pAl = Al + (size_t)(m0 + lrow) * lda + lseg;
    const __nv_bfloat16* pBh = Bh + (size_t)(n0 + lrow) * ldb + lseg;
    const __nv_bfloat16* pBl = Bl + (size_t)(n0 + lrow) * ldb + lseg;

    const int nch = Klen / BK;

    // ldmatrix base offsets (within a tile)
    const u32 lm_a0 = (u32)((warp_m + (lane & 15)) * LDSS + (lane >> 4) * 8) * 2;
    const u32 lm_b0 = (u32)((warp_n + (lane & 15)) * LDSS + (lane >> 4) * 8) * 2;

    float acc[4][8][4];
#pragma unroll
    for (int i = 0; i < 4; ++i)
#pragma unroll
        for (int j = 0; j < 8; ++j)
#pragma unroll
            for (int q = 0; q < 4; ++q) acc[i][j][q] = 0.0f;

    // ---- prologue: load chunk 0 ----
    {
        const u32 ba = sbase;
#pragma unroll
        for (int p = 0; p < 8; ++p) {
            const u32 d = ba + dst_off + (u32)(32 * p * LDSS) * 2;
            cp_async16(d + OFF_AH, pAh + (size_t)(32 * p) * lda);
            cp_async16(d + OFF_AL, pAl + (size_t)(32 * p) * lda);
        }
#pragma unroll
        for (int p = 0; p < 4; ++p) {
            const u32 d = ba + dst_off + (u32)(32 * p * LDSS) * 2;
            cp_async16(d + OFF_BH, pBh + (size_t)(32 * p) * ldb);
            cp_async16(d + OFF_BL, pBl + (size_t)(32 * p) * ldb);
        }
        CP_COMMIT();
    }

    for (int c = 0; c < nch; ++c) {
        // issue loads for chunk c+1 into the other buffer
        if (c + 1 < nch) {
            const u32 ba = sbase + ((c + 1) & 1) * BUF_B;
            const int k0 = (c + 1) * BK;
#pragma unroll
            for (int p = 0; p < 8; ++p) {
                const u32 d = ba + dst_off + (u32)(32 * p * LDSS) * 2;
                cp_async16(d + OFF_AH, pAh + (size_t)(32 * p) * lda + k0);
                cp_async16(d + OFF_AL, pAl + (size_t)(32 * p) * lda + k0);
            }
#pragma unroll
            for (int p = 0; p < 4; ++p) {
                const u32 d = ba + dst_off + (u32)(32 * p * LDSS) * 2;
                cp_async16(d + OFF_BH, pBh + (size_t)(32 * p) * ldb + k0);
                cp_async16(d + OFF_BL, pBl + (size_t)(32 * p) * ldb + k0);
            }
            CP_COMMIT();
            CP_WAIT(1);   // chunk c complete, c+1 in flight
        } else {
            CP_WAIT(0);
        }
        __syncthreads();

        const u32 ba = sbase + (c & 1) * BUF_B;
        const u32 aAh = ba + OFF_AH + lm_a0;
        const u32 aAl = ba + OFF_AL + lm_a0;
        const u32 aBh = ba + OFF_BH + lm_b0;
        const u32 aBl = ba + OFF_BL + lm_b0;

#pragma unroll
        for (int ks = 0; ks < BK / 16; ++ks) {
            const u32 ko = (u32)(ks * 16) * 2;
            u32 bh[8][2], bl[8][2];
#pragma unroll
            for (int g = 0; g < 4; ++g) {   // 16 n-rows per ldmatrix.x4
                u32 r0, r1, r2, r3;
                ldmx4(aBh + ko + (u32)(g * 16 * LDSS) * 2, r0, r1, r2, r3);
                bh[2 * g][0] = r0; bh[2 * g][1] = r2;
                bh[2 * g + 1][0] = r1; bh[2 * g + 1][1] = r3;
                ldmx4(aBl + ko + (u32)(g * 16 * LDSS) * 2, r0, r1, r2, r3);
                bl[2 * g][0] = r0; bl[2 * g][1] = r2;
                bl[2 * g + 1][0] = r1; bl[2 * g + 1][1] = r3;
            }
#pragma unroll
            for (int mf = 0; mf < 4; ++mf) {
                u32 ah[4], al[4];
                ldmx4(aAh + ko + (u32)(mf * 16 * LDSS) * 2,
                      ah[0], ah[1], ah[2], ah[3]);
                ldmx4(aAl + ko + (u32)(mf * 16 * LDSS) * 2,
                      al[0], al[1], al[2], al[3]);
#pragma unroll
                for (int nf = 0; nf < 8; ++nf) {
                    mma16816(acc[mf][nf], ah, bh[nf]);
                    mma16816(acc[mf][nf], ah, bl[nf]);
                    mma16816(acc[mf][nf], al, bh[nf]);
                }
            }
        }
        __syncthreads();
    }

    // ---- epilogue ----
    const int erow = lane >> 2;
    const int ecol = (lane & 3) * 2;
#pragma unroll
    for (int mf = 0; mf < 4; ++mf) {
        const int rbase = m0 + warp_m + mf * 16 + erow;
#pragma unroll
        for (int nf = 0; nf < 8; ++nf) {
            const int ccol = n0 + warp_n + nf * 8 + ecol;
            if (MODE == 0) {
                float2 v0, v1;
                v0.x = acc[mf][nf][0] * scale; v0.y = acc[mf][nf][1] * scale;
                v1.x = acc[mf][nf][2] * scale; v1.y = acc[mf][nf][3] * scale;
                *(float2*)(Cf + (size_t)rbase * ldc + ccol) = v0;
                *(float2*)(Cf + (size_t)(rbase + 8) * ldc + ccol) = v1;
            } else {
                __nv_bfloat16 h0, l0, h1, l1;
                split2(acc[mf][nf][0], h0, l0);
                split2(acc[mf][nf][1], h1, l1);
                *(__nv_bfloat162*)(Ch + (size_t)rbase * ldc + ccol) = __halves2bfloat162(h0, h1);
                *(__nv_bfloat162*)(Cl + (size_t)rbase * ldc + ccol) = __halves2bfloat162(l0, l1);
                split2(acc[mf][nf][2], h0, l0);
                split2(acc[mf][nf][3], h1, l1);
                *(__nv_bfloat162*)(Ch + (size_t)(rbase + 8) * ldc + ccol) = __halves2bfloat162(h0, h1);
                *(__nv_bfloat162*)(Cl + (size_t)(rbase + 8) * ldc + ccol) = __halves2bfloat162(l0, l1);
            }
        }
    }
}

// ---------------- prep kernels ----------------
__global__ void split_x_kernel(const float* __restrict__ x) {
    const int n = 8192 * 1024;
    for (int i = blockIdx.x * blockDim.x + threadIdx.x; i < n; i += gridDim.x * blockDim.x) {
        __nv_bfloat16 h, l;
        split2(x[i], h, l);
        g_xh[i] = h; g_xl[i] = l;
    }
}

__global__ void wt_kernel(const float* __restrict__ Wq, const float* __restrict__ Wk,
                          const float* __restrict__ Wv) {
    __shared__ float t[32][33];
    const float* W = (blockIdx.z == 0) ? Wq : (blockIdx.z == 1) ? Wk : Wv;
    __nv_bfloat16* Th = g_WTh + (size_t)blockIdx.z * 1024 * 1024;
    __nv_bfloat16* Tl = g_WTl + (size_t)blockIdx.z * 1024 * 1024;
    const int n0 = blockIdx.x * 32, k0 = blockIdx.y * 32;
    const int tx = threadIdx.x, ty = threadIdx.y;
#pragma unroll
    for (int i = 0; i < 4; ++i)
        t[ty + i * 8][tx] = W[(size_t)(k0 + ty + i * 8) * 1024 + n0 + tx];
    __syncthreads();
#pragma unroll
    for (int i = 0; i < 4; ++i) {
        __nv_bfloat16 h, l;
        split2(t[tx][ty + i * 8], h, l);  // = W[k0+tx][n0+ty+i*8]
        const size_t o = (size_t)(n0 + ty + i * 8) * 1024 + k0 + tx;
        Th[o] = h; Tl[o] = l;
    }
}

__global__ void vt_kernel() {
    __shared__ float t[32][33];
    const int b = blockIdx.z;
    const float* V = g_V + (size_t)b * 2048 * 1024;
    __nv_bfloat16* Th = g_VTh + (size_t)b * 1024 * 2048;
    __nv_bfloat16* Tl = g_VTl + (size_t)b * 1024 * 2048;
    const int e0 = blockIdx.x * 32, k0 = blockIdx.y * 32;
    const int tx = threadIdx.x, ty = threadIdx.y;
#pragma unroll
    for (int i = 0; i < 4; ++i)
        t[ty + i * 8][tx] = V[(size_t)(k0 + ty + i * 8) * 1024 + e0 + tx];
    __syncthreads();
#pragma unroll
    for (int i = 0; i < 4; ++i) {
        __nv_bfloat16 h, l;
        split2(t[tx][ty + i * 8], h, l);  // = V[k0+tx][e0+ty+i*8]
        const size_t o = (size_t)(e0 + ty + i * 8) * 2048 + k0 + tx;
        Th[o] = h; Tl[o] = l;
    }
}

// ---------------- GEMM kernels ----------------
__global__ void __launch_bounds__(TPB, 1)
proj_kernel() {
    const int z = blockIdx.z;
    const int m0 = blockIdx.y * 256;
    const int n0 = blockIdx.x * 128;
    const __nv_bfloat16* Bh = g_WTh + (size_t)z * 1024 * 1024;
    const __nv_bfloat16* Bl = g_WTl + (size_t)z * 1024 * 1024;
    if (z == 0)
        gemm_core<1>(g_xh, g_xl, 1024, Bh, Bl, 1024, m0, n0, 1024, 1.0f,
                     nullptr, g_Qh, g_Ql, 1024);
    else if (z == 1)
        gemm_core<1>(g_xh, g_xl, 1024, Bh, Bl, 1024, m0, n0, 1024, 1.0f,
                     nullptr, g_Kh, g_Kl, 1024);
    else
        gemm_core<0>(g_xh, g_xl, 1024, Bh, Bl, 1024, m0, n0, 1024, 1.0f,
                     g_V, nullptr, nullptr, 1024);
}

__global__ void __launch_bounds__(TPB, 1)
score_kernel() {
    const int kb = blockIdx.x, qb = blockIdx.y, b = blockIdx.z;
    if (kb > 2 * qb + 1) return;  // block fully above diagonal
    const size_t qo = (size_t)b * 2048 * 1024;
    gemm_core<0>(g_Qh + qo, g_Ql + qo, 1024, g_Kh + qo, g_Kl + qo, 1024,
                 qb * 256, kb * 128, 1024, 0.03125f,
                 g_S + (size_t)b * 2048 * 2048, nullptr, nullptr, 2048);
}

__global__ void __launch_bounds__(TPB, 1)
pv_kernel(float* __restrict__ out) {
    const int nb = blockIdx.x, qb = blockIdx.y, b = blockIdx.z;
    const size_t po = (size_t)b * 2048 * 2048;
    const size_t vo = (size_t)b * 1024 * 2048;
    gemm_core<0>(g_Ph + po, g_Pl + po, 2048, g_VTh + vo, g_VTl + vo, 2048,
                 qb * 256, nb * 128, (qb + 1) * 256, 1.0f,
                 out + (size_t)b * 2048 * 1024, nullptr, nullptr, 1024);
}

// ---------------- softmax ----------------
__global__ void softmax_kernel() {
    const int q = blockIdx.x, b = blockIdx.y;
    float* row = g_S + ((size_t)b * 2048 + q) * 2048;
    __nv_bfloat16* ph = g_Ph + ((size_t)b * 2048 + q) * 2048;
    __nv_bfloat16* pl = g_Pl + ((size_t)b * 2048 + q) * 2048;
    const int len = q + 1;
    const int tid = threadIdx.x;
    __shared__ float red[TPB];

    float m = -1e30f;
    for (int i = tid; i < len; i += TPB) m = fmaxf(m, row[i]);
    red[tid] = m;
    __syncthreads();
#pragma unroll
    for (int s = TPB / 2; s > 0; s >>= 1) {
        if (tid < s) red[tid] = fmaxf(red[tid], red[tid + s]);
        __syncthreads();
    }
    m = red[0];
    __syncthreads();

    float sum = 0.0f;
    for (int i = tid; i < len; i += TPB) {
        float e = __expf(row[i] - m);
        row[i] = e;
        sum += e;
    }
    red[tid] = sum;
    __syncthreads();
#pragma unroll
    for (int s = TPB / 2; s > 0; s >>= 1) {
        if (tid < s) red[tid] += red[tid + s];
        __syncthreads();
    }
    const float inv = 1.0f / red[0];
    __syncthreads();

    const __nv_bfloat16 z = __float2bfloat16(0.0f);
    for (int i = tid; i < len; i += TPB) {
        __nv_bfloat16 h, l;
        split2(row[i] * inv, h, l);
        ph[i] = h; pl[i] = l;
    }
    const int klim = ((q >> 8) + 1) << 8;  // zero up to 256-tile boundary (pv tile)
    for (int i = len + tid; i < klim; i += TPB) { ph[i] = z; pl[i] = z; }
}

// ---------------- launch ----------------
extern "C" void kernel_launch(void* const* d_in, const int* in_sizes, int n_in,
                              void* d_out, int out_size) {
    const float* x  = (const float*)d_in[0];
    const float* Wq = (const float*)d_in[1];
    const float* Wk = (const float*)d_in[2];
    const float* Wv = (const float*)d_in[3];
    float* out = (float*)d_out;

    cudaFuncSetAttribute(proj_kernel,  cudaFuncAttributeMaxDynamicSharedMemorySize, GEMM_SMEM);
    cudaFuncSetAttribute(score_kernel, cudaFuncAttributeMaxDynamicSharedMemorySize, GEMM_SMEM);
    cudaFuncSetAttribute(pv_kernel,    cudaFuncAttributeMaxDynamicSharedMemorySize, GEMM_SMEM);

    split_x_kernel<<<4096, 256>>>(x);
    wt_kernel<<<dim3(32, 32, 3), dim3(32, 8)>>>(Wq, Wk, Wv);
    proj_kernel<<<dim3(8, 32, 3), TPB, GEMM_SMEM>>>();
    vt_kernel<<<dim3(32, 64, 4), dim3(32, 8)>>>();
    score_kernel<<<dim3(16, 8, 4), TPB, GEMM_SMEM>>>();
    softmax_kernel<<<dim3(2048, 4), TPB>>>();
    pv_kernel<<<dim3(8, 8, 4), TPB, GEMM_SMEM>>>(out);
}